// round 7
// baseline (speedup 1.0000x reference)
#include <cuda_runtime.h>
#include <cuda_fp16.h>
#include <cstdint>
#include <cstddef>

#define BB 16
#define NN 96
#define DD 256
#define MROWS (BB * NN * NN)          // 147456
#define NCOLS (NN * DD)               // 24576

// Scratch (allocation-free device globals)
__device__ __half g_h1[(size_t)MROWS * DD];
__device__ __half g_h2[(size_t)MROWS * DD];
__device__ __half g_W1h[DD * DD];    // transposed [n][k] fp16
__device__ __half g_W2h[DD * DD];    // transposed [n][k] fp16
__device__ __half g_Ah[BB * NN * NN];

// ---------------------------------------------------------------------------
// helpers
// ---------------------------------------------------------------------------
__device__ __forceinline__ uint32_t packh2(float a, float b) {
    __half2 h = __floats2half2_rn(a, b);
    return *reinterpret_cast<uint32_t*>(&h);
}

__device__ __forceinline__ void mma16(float* c, const uint32_t* a, const uint32_t* b) {
    asm volatile("mma.sync.aligned.m16n8k16.row.col.f32.f16.f16.f32 "
        "{%0,%1,%2,%3}, {%4,%5,%6,%7}, {%8,%9}, {%0,%1,%2,%3};"
        : "+f"(c[0]), "+f"(c[1]), "+f"(c[2]), "+f"(c[3])
        : "r"(a[0]), "r"(a[1]), "r"(a[2]), "r"(a[3]), "r"(b[0]), "r"(b[1]));
}

__device__ __forceinline__ void ldsm4(uint32_t* r, uint32_t addr) {
    asm volatile("ldmatrix.sync.aligned.m8n8.x4.shared.b16 {%0,%1,%2,%3}, [%4];"
        : "=r"(r[0]), "=r"(r[1]), "=r"(r[2]), "=r"(r[3]) : "r"(addr));
}

__device__ __forceinline__ void ldsm4t(uint32_t* r, uint32_t addr) {
    asm volatile("ldmatrix.sync.aligned.m8n8.x4.trans.shared.b16 {%0,%1,%2,%3}, [%4];"
        : "=r"(r[0]), "=r"(r[1]), "=r"(r[2]), "=r"(r[3]) : "r"(addr));
}

__device__ __forceinline__ void cpa16(uint32_t dst, const void* src) {
    asm volatile("cp.async.cg.shared.global [%0], [%1], 16;\n" :: "r"(dst), "l"(src));
}
__device__ __forceinline__ void cpa_commit() {
    asm volatile("cp.async.commit_group;\n");
}
template <int N>
__device__ __forceinline__ void cpa_wait() {
    asm volatile("cp.async.wait_group %0;\n" :: "n"(N));
}

// ---------------------------------------------------------------------------
// prepasses
// ---------------------------------------------------------------------------
__global__ void transpose_cvt_kernel(const float* __restrict__ src,
                                     __half* __restrict__ dst) {
    __shared__ float t[32][33];
    int bx = blockIdx.x * 32;   // n base
    int by = blockIdx.y * 32;   // k base
    int x = threadIdx.x, y0 = threadIdx.y;
#pragma unroll
    for (int r = 0; r < 32; r += 8)
        t[y0 + r][x] = src[(size_t)(by + y0 + r) * DD + bx + x];
    __syncthreads();
#pragma unroll
    for (int r = 0; r < 32; r += 8)
        dst[(size_t)(bx + y0 + r) * DD + by + x] = __float2half_rn(t[x][y0 + r]);
}

__global__ void cvt_half_kernel(const float4* __restrict__ src,
                                uint2* __restrict__ dst, int n4) {
    int i = blockIdx.x * blockDim.x + threadIdx.x;
    if (i < n4) {
        float4 v = src[i];
        uint2 o;
        o.x = packh2(v.x, v.y);
        o.y = packh2(v.z, v.w);
        dst[i] = o;
    }
}

// ---------------------------------------------------------------------------
// MLP GEMM: C_half[M,256] = act(A[M,256] @ W + bias), optional row mask.
// BM=64, BN=256 (full D), BK=64, 128 threads (4 warps), warp tile 64x64.
// 2 CTAs/SM (regs ~210, smem 80KB). fp16 smem, m16n8k16, ldmatrix.
// CONV=1: A fp32 (X): early-issued LDG + cvt + STS (latency hidden by MMAs).
// CONV=0: A fp16 (h1) via cp.async.
// ---------------------------------------------------------------------------
template <int CONV>
__global__ __launch_bounds__(128)
void mlp_h2(const void* __restrict__ Ain, const __half* __restrict__ Wt,
            const float* __restrict__ bias, const int* __restrict__ mask,
            __half* __restrict__ C)
{
    extern __shared__ __align__(16) char smem[];
    const uint32_t sBase = (uint32_t)__cvta_generic_to_shared(smem);
    const uint32_t aBase = sBase;             // + stage*8192   (64 rows x 128B)
    const uint32_t bBase = sBase + 16384;     // + stage*32768  (256 rows x 128B)

    const int tid  = threadIdx.x;
    const int lane = tid & 31;
    const int warp = tid >> 5;                // 0..3
    const int grp  = lane >> 2;
    const int c4   = lane & 3;
    const int warpN = warp * 64;
    const int rowBase = blockIdx.x * 64;

    const float*  Af = (const float*)Ain;
    const __half* Ah = (const __half*)Ain;

    // A loader: row = tid>>1 (0..63), chunks (tid&1)*4 + j
    const int aRow = tid >> 1;
    const int aChB = (tid & 1) * 4;

    uint4 regA[4];

    float acc[4][8][4];
#pragma unroll
    for (int i = 0; i < 4; i++)
#pragma unroll
        for (int j = 0; j < 8; j++)
#pragma unroll
            for (int r = 0; r < 4; r++) acc[i][j][r] = 0.0f;

    auto ldgA = [&](int it) {
#pragma unroll
        for (int j = 0; j < 4; j++) {
            const float* p = Af + (size_t)(rowBase + aRow) * DD + it * 64 + (aChB + j) * 8;
            float4 u = *reinterpret_cast<const float4*>(p);
            float4 v = *reinterpret_cast<const float4*>(p + 4);
            regA[j].x = packh2(u.x, u.y);
            regA[j].y = packh2(u.z, u.w);
            regA[j].z = packh2(v.x, v.y);
            regA[j].w = packh2(v.z, v.w);
        }
    };
    auto stsA = [&](int stage) {
#pragma unroll
        for (int j = 0; j < 4; j++) {
            int ch = aChB + j;
            *reinterpret_cast<uint4*>(smem + stage * 8192 + aRow * 128 +
                                      ((ch ^ (aRow & 7)) << 4)) = regA[j];
        }
    };
    auto cpaA = [&](int it, int stage) {
#pragma unroll
        for (int j = 0; j < 4; j++) {
            int ch = aChB + j;
            cpa16(aBase + stage * 8192 + aRow * 128 + ((ch ^ (aRow & 7)) << 4),
                  Ah + (size_t)(rowBase + aRow) * DD + it * 64 + ch * 8);
        }
    };
    auto cpaB = [&](int it, int stage) {
#pragma unroll
        for (int rr = 0; rr < 2; rr++) {
            int n = tid + 128 * rr;
#pragma unroll
            for (int j = 0; j < 8; j++)
                cpa16(bBase + stage * 32768 + n * 128 + ((j ^ (n & 7)) << 4),
                      Wt + (size_t)n * DD + it * 64 + j * 8);
        }
    };

    // ---- prologue ----
    if (CONV) {
        cpaB(0, 0); cpa_commit();
        cpaB(1, 1); cpa_commit();
        ldgA(0); stsA(0);
        ldgA(1); stsA(1);
        ldgA(2);                       // regA = tile2
    } else {
        cpaA(0, 0); cpaB(0, 0); cpa_commit();
        cpaA(1, 1); cpaB(1, 1); cpa_commit();
    }
    cpa_wait<1>();
    __syncthreads();

    // ---- mainloop: 4 tiles of BK=64 ----
#pragma unroll 1
    for (int it = 0; it < 4; it++) {
        const int s = it & 1;
        const uint32_t aSt = aBase + s * 8192;
        const uint32_t bSt = bBase + s * 32768;

#pragma unroll
        for (int ks = 0; ks < 4; ks++) {
            uint32_t afr[4][4];
#pragma unroll
            for (int mt = 0; mt < 4; mt++) {
                int m  = mt * 16 + (lane & 15);
                int ch = 2 * ks + (lane >> 4);
                ldsm4(afr[mt], aSt + m * 128 + ((ch ^ (m & 7)) << 4));
            }
            uint32_t bfr[4][4];
#pragma unroll
            for (int np = 0; np < 4; np++) {
                int n  = warpN + np * 16 + 8 * (lane >> 4) + (lane & 7);
                int ch = 2 * ks + ((lane >> 3) & 1);
                ldsm4(bfr[np], bSt + n * 128 + ((ch ^ (n & 7)) << 4));
            }
#pragma unroll
            for (int mt = 0; mt < 4; mt++)
#pragma unroll
                for (int np = 0; np < 4; np++) {
                    mma16(acc[mt][2 * np + 0], afr[mt], bfr[np] + 0);
                    mma16(acc[mt][2 * np + 1], afr[mt], bfr[np] + 2);
                }
        }
        if (it == 3) break;
        __syncthreads();                       // stage s free

        if (CONV) {
            if (it <= 1) stsA(s);              // tile it+2 from regA
            if (it == 0) ldgA(3);              // latency hidden by compute(it=1)
            if (it <= 1) { cpaB(it + 2, s); cpa_commit(); cpa_wait<1>(); }
            else         { cpa_wait<0>(); }
        } else {
            if (it <= 1) { cpaA(it + 2, s); cpaB(it + 2, s); cpa_commit(); cpa_wait<1>(); }
            else         { cpa_wait<0>(); }
        }
        __syncthreads();
    }

    // ---- epilogue: bias + relu (+mask), store fp16 ----
#pragma unroll
    for (int mt = 0; mt < 4; mt++) {
        int rr = rowBase + mt * 16 + grp;
#pragma unroll
        for (int pr = 0; pr < 2; pr++) {
            int r = rr + 8 * pr;
            float mv = 1.0f;
            if (mask != nullptr) mv = (mask[r] != 0) ? 1.0f : 0.0f;
#pragma unroll
            for (int nt = 0; nt < 8; nt++) {
                int col = warpN + nt * 8 + 2 * c4;
                float2 bb = *reinterpret_cast<const float2*>(bias + col);
                float v0 = fmaxf(acc[mt][nt][2 * pr + 0] + bb.x, 0.0f) * mv;
                float v1 = fmaxf(acc[mt][nt][2 * pr + 1] + bb.y, 0.0f) * mv;
                *reinterpret_cast<__half2*>(C + (size_t)r * DD + col) =
                    __floats2half2_rn(v0, v1);
            }
        }
    }
}

// ---------------------------------------------------------------------------
// Message passing: Out[b] (96 x 24576 fp32) = Ah[b] (96x96 fp16) @ H[b] (96x24576 fp16)
// 256 threads (8 warps), BN=128 col tile, BK=32 (3 tiles), warp tile 48x32.
// ---------------------------------------------------------------------------
__global__ __launch_bounds__(256)
void msg_h(const __half* __restrict__ Aall, const __half* __restrict__ H,
           float* __restrict__ Out)
{
    __shared__ __align__(16) char sm[96 * 208 + 2 * 8192];
    const uint32_t aB = (uint32_t)__cvta_generic_to_shared(sm);
    const uint32_t bB = aB + 19968;

    const int b = blockIdx.y;
    const int colBase = blockIdx.x * 128;
    const __half* Aab = Aall + (size_t)b * NN * NN;
    const __half* Hb  = H    + (size_t)b * NN * NCOLS;
    float*        Ob  = Out  + (size_t)b * NN * NCOLS;

    const int tid  = threadIdx.x;
    const int lane = tid & 31;
    const int warp = tid >> 5;
    const int grp  = lane >> 2;
    const int c4   = lane & 3;
    const int warpM = (warp >> 2) * 48;
    const int warpN = (warp & 3) * 32;

    const int bkr = tid >> 3;
    const int bch = tid & 7;
    auto cpaBt = [&](int it, int stage) {
#pragma unroll
        for (int j = 0; j < 2; j++) {
            int ch = bch + 8 * j;
            cpa16(bB + stage * 8192 + bkr * 256 + ((ch ^ (bkr & 7)) << 4),
                  Hb + (size_t)(it * 32 + bkr) * NCOLS + colBase + ch * 8);
        }
    };

    for (int idx = tid; idx < 96 * 12; idx += 256) {
        int row = idx / 12, ch = idx % 12;
        cpa16(aB + row * 208 + ch * 16, Aab + row * 96 + ch * 8);
    }
    cpaBt(0, 0); cpa_commit();
    cpaBt(1, 1); cpa_commit();
    cpa_wait<1>();
    __syncthreads();

    float acc[3][4][4];
#pragma unroll
    for (int i = 0; i < 3; i++)
#pragma unroll
        for (int j = 0; j < 4; j++)
#pragma unroll
            for (int r = 0; r < 4; r++) acc[i][j][r] = 0.0f;

#pragma unroll 1
    for (int it = 0; it < 3; it++) {
        const int st = it & 1;
#pragma unroll
        for (int sl = 0; sl < 2; sl++) {
            const int s = 2 * it + sl;
            uint32_t afr[3][4];
#pragma unroll
            for (int mt = 0; mt < 3; mt++) {
                int m  = warpM + mt * 16 + (lane & 15);
                int ch = 2 * s + (lane >> 4);
                ldsm4(afr[mt], aB + m * 208 + ch * 16);
            }
            uint32_t bfr[2][4];
#pragma unroll
            for (int np = 0; np < 2; np++) {
                int kl  = sl * 16 + (lane & 7) + 8 * ((lane >> 3) & 1);
                int chn = (warpN >> 3) + 2 * np + (lane >> 4);
                ldsm4t(bfr[np], bB + st * 8192 + kl * 256 + ((chn ^ (kl & 7)) << 4));
            }
#pragma unroll
            for (int mt = 0; mt < 3; mt++)
#pragma unroll
                for (int np = 0; np < 2; np++) {
                    mma16(acc[mt][2 * np + 0], afr[mt], bfr[np] + 0);
                    mma16(acc[mt][2 * np + 1], afr[mt], bfr[np] + 2);
                }
        }
        __syncthreads();
        if (it + 2 <= 2) { cpaBt(it + 2, st); cpa_commit(); cpa_wait<1>(); }
        else             { cpa_wait<0>(); }
        __syncthreads();
    }

#pragma unroll
    for (int mt = 0; mt < 3; mt++) {
        int rr = warpM + mt * 16 + grp;
#pragma unroll
        for (int pr = 0; pr < 2; pr++) {
            int r = rr + 8 * pr;
#pragma unroll
            for (int nt = 0; nt < 4; nt++) {
                int col = colBase + warpN + nt * 8 + 2 * c4;
                *reinterpret_cast<float2*>(Ob + (size_t)r * NCOLS + col) =
                    make_float2(acc[mt][nt][2 * pr + 0], acc[mt][nt][2 * pr + 1]);
            }
        }
    }
}

// ---------------------------------------------------------------------------
// kernel_launch: inputs X, mask, A, W1, b1, W2, b2
// ---------------------------------------------------------------------------
extern "C" void kernel_launch(void* const* d_in, const int* in_sizes, int n_in,
                              void* d_out, int out_size)
{
    const float* X    = (const float*)d_in[0];
    const int*   mask = (const int*)d_in[1];
    const float* Aadj = (const float*)d_in[2];
    const float* W1   = (const float*)d_in[3];
    const float* b1   = (const float*)d_in[4];
    const float* W2   = (const float*)d_in[5];
    const float* b2   = (const float*)d_in[6];
    float*       out  = (float*)d_out;

    __half *h1, *h2, *w1h, *w2h, *ah;
    cudaGetSymbolAddress((void**)&h1,  g_h1);
    cudaGetSymbolAddress((void**)&h2,  g_h2);
    cudaGetSymbolAddress((void**)&w1h, g_W1h);
    cudaGetSymbolAddress((void**)&w2h, g_W2h);
    cudaGetSymbolAddress((void**)&ah,  g_Ah);

    const int MLP_SMEM = 81920;   // 80KB -> 2 CTAs/SM
    cudaFuncSetAttribute(mlp_h2<1>, cudaFuncAttributeMaxDynamicSharedMemorySize, MLP_SMEM);
    cudaFuncSetAttribute(mlp_h2<0>, cudaFuncAttributeMaxDynamicSharedMemorySize, MLP_SMEM);

    // prepasses: transpose+cvt W1/W2 to fp16 [n][k]; cvt Aadj to fp16
    {
        dim3 tg(DD / 32, DD / 32);
        dim3 tb(32, 8);
        transpose_cvt_kernel<<<tg, tb>>>(W1, w1h);
        transpose_cvt_kernel<<<tg, tb>>>(W2, w2h);
        int a4 = (BB * NN * NN) / 4;
        cvt_half_kernel<<<(a4 + 255) / 256, 256>>>((const float4*)Aadj, (uint2*)ah, a4);
    }

    // layer 1: h1 = half(relu(half(X) @ W1 + b1))
    mlp_h2<1><<<MROWS / 64, 128, MLP_SMEM>>>(X, w1h, b1, nullptr, h1);
    // layer 2: h2 = half(mask * relu(h1 @ W2 + b2))
    mlp_h2<0><<<MROWS / 64, 128, MLP_SMEM>>>(h1, w2h, b2, mask, h2);
    // message passing: out[b] = Ah[b] @ h2[b]
    {
        dim3 grid(NCOLS / 128, BB);   // (192, 16)
        msg_h<<<grid, 256>>>(ah, h2, out);
    }
}

// round 8
// speedup vs baseline: 1.3875x; 1.3875x over previous
#include <cuda_runtime.h>
#include <cuda_fp16.h>
#include <cstdint>
#include <cstddef>

#define BB 16
#define NN 96
#define DD 256
#define MROWS (BB * NN * NN)          // 147456
#define NCOLS (NN * DD)               // 24576

// Scratch (allocation-free device globals)
__device__ __half g_h1[(size_t)MROWS * DD];
__device__ __half g_h2[(size_t)MROWS * DD];
__device__ __half g_W1h[DD * DD];    // transposed [n][k] fp16
__device__ __half g_W2h[DD * DD];    // transposed [n][k] fp16
__device__ __half g_Ah[BB * NN * NN];

// ---------------------------------------------------------------------------
// helpers
// ---------------------------------------------------------------------------
__device__ __forceinline__ uint32_t packh2(float a, float b) {
    __half2 h = __floats2half2_rn(a, b);
    return *reinterpret_cast<uint32_t*>(&h);
}

__device__ __forceinline__ void mma16(float* c, const uint32_t* a, const uint32_t* b) {
    asm volatile("mma.sync.aligned.m16n8k16.row.col.f32.f16.f16.f32 "
        "{%0,%1,%2,%3}, {%4,%5,%6,%7}, {%8,%9}, {%0,%1,%2,%3};"
        : "+f"(c[0]), "+f"(c[1]), "+f"(c[2]), "+f"(c[3])
        : "r"(a[0]), "r"(a[1]), "r"(a[2]), "r"(a[3]), "r"(b[0]), "r"(b[1]));
}

__device__ __forceinline__ void ldsm4(uint32_t* r, uint32_t addr) {
    asm volatile("ldmatrix.sync.aligned.m8n8.x4.shared.b16 {%0,%1,%2,%3}, [%4];"
        : "=r"(r[0]), "=r"(r[1]), "=r"(r[2]), "=r"(r[3]) : "r"(addr));
}

__device__ __forceinline__ void ldsm4t(uint32_t* r, uint32_t addr) {
    asm volatile("ldmatrix.sync.aligned.m8n8.x4.trans.shared.b16 {%0,%1,%2,%3}, [%4];"
        : "=r"(r[0]), "=r"(r[1]), "=r"(r[2]), "=r"(r[3]) : "r"(addr));
}

__device__ __forceinline__ void cpa16(uint32_t dst, const void* src) {
    asm volatile("cp.async.cg.shared.global [%0], [%1], 16;\n" :: "r"(dst), "l"(src));
}
__device__ __forceinline__ void cpa_commit() {
    asm volatile("cp.async.commit_group;\n");
}
template <int N>
__device__ __forceinline__ void cpa_wait() {
    asm volatile("cp.async.wait_group %0;\n" :: "n"(N));
}

// ---------------------------------------------------------------------------
// prepasses
// ---------------------------------------------------------------------------
__global__ void transpose_cvt_kernel(const float* __restrict__ src,
                                     __half* __restrict__ dst) {
    __shared__ float t[32][33];
    int bx = blockIdx.x * 32;   // n base
    int by = blockIdx.y * 32;   // k base
    int x = threadIdx.x, y0 = threadIdx.y;
#pragma unroll
    for (int r = 0; r < 32; r += 8)
        t[y0 + r][x] = src[(size_t)(by + y0 + r) * DD + bx + x];
    __syncthreads();
#pragma unroll
    for (int r = 0; r < 32; r += 8)
        dst[(size_t)(bx + y0 + r) * DD + by + x] = __float2half_rn(t[x][y0 + r]);
}

__global__ void cvt_half_kernel(const float4* __restrict__ src,
                                uint2* __restrict__ dst, int n4) {
    int i = blockIdx.x * blockDim.x + threadIdx.x;
    if (i < n4) {
        float4 v = src[i];
        uint2 o;
        o.x = packh2(v.x, v.y);
        o.y = packh2(v.z, v.w);
        dst[i] = o;
    }
}

// ---------------------------------------------------------------------------
// MLP GEMM: C_half[M,256] = act(A[M,256] @ W + bias), optional row mask.
// BM=128, BN=256 (full D), BK=64, 512 threads (16 warps), warp tile 64x32
// (warp grid 2M x 8N). acc = 64 regs/thread -> ~115 regs -> 16 warps/SM.
// fp16 smem, m16n8k16, ldmatrix, cp.async double-buffer.
// CONV=1: A fp32 (X) converted in loader (LDG+cvt+STS register staging).
// CONV=0: A fp16 (h1) via cp.async.
// smem: As 2 x 16KB, Bs 2 x 32KB = 96KB.
// ---------------------------------------------------------------------------
template <int CONV>
__global__ __launch_bounds__(512)
void mlp_h3(const void* __restrict__ Ain, const __half* __restrict__ Wt,
            const float* __restrict__ bias, const int* __restrict__ mask,
            __half* __restrict__ C)
{
    extern __shared__ __align__(16) char smem[];
    const uint32_t sBase = (uint32_t)__cvta_generic_to_shared(smem);
    const uint32_t aBase = sBase;             // + stage*16384
    const uint32_t bBase = sBase + 32768;     // + stage*32768

    const int tid  = threadIdx.x;
    const int lane = tid & 31;
    const int warp = tid >> 5;                // 0..15
    const int grp  = lane >> 2;
    const int c4   = lane & 3;
    const int warpM = (warp >> 3) * 64;       // 0 / 64
    const int warpN = (warp & 7) * 32;        // 0..224
    const int rowBase = blockIdx.x * 128;

    const float*  Af = (const float*)Ain;
    const __half* Ah = (const __half*)Ain;

    // A loader: 512 thr, 128 rows x 8 chunks -> 2 chunks/thread
    const int aRow = tid >> 2;                // 0..127
    const int aChB = (tid & 3) * 2;           // 0,2,4,6
    // B loader: 256 rows x 8 chunks -> 4 chunks/thread
    const int bRow = tid >> 1;                // 0..255
    const int bChB = (tid & 1) * 4;           // 0,4

    uint4 regA[2];

    float acc[4][4][4];
#pragma unroll
    for (int i = 0; i < 4; i++)
#pragma unroll
        for (int j = 0; j < 4; j++)
#pragma unroll
            for (int r = 0; r < 4; r++) acc[i][j][r] = 0.0f;

    auto ldgA = [&](int it) {
#pragma unroll
        for (int j = 0; j < 2; j++) {
            const float* p = Af + (size_t)(rowBase + aRow) * DD + it * 64 + (aChB + j) * 8;
            float4 u = *reinterpret_cast<const float4*>(p);
            float4 v = *reinterpret_cast<const float4*>(p + 4);
            regA[j].x = packh2(u.x, u.y);
            regA[j].y = packh2(u.z, u.w);
            regA[j].z = packh2(v.x, v.y);
            regA[j].w = packh2(v.z, v.w);
        }
    };
    auto stsA = [&](int stage) {
#pragma unroll
        for (int j = 0; j < 2; j++) {
            int ch = aChB + j;
            *reinterpret_cast<uint4*>(smem + stage * 16384 + aRow * 128 +
                                      ((ch ^ (aRow & 7)) << 4)) = regA[j];
        }
    };
    auto cpaA = [&](int it, int stage) {
#pragma unroll
        for (int j = 0; j < 2; j++) {
            int ch = aChB + j;
            cpa16(aBase + stage * 16384 + aRow * 128 + ((ch ^ (aRow & 7)) << 4),
                  Ah + (size_t)(rowBase + aRow) * DD + it * 64 + ch * 8);
        }
    };
    auto cpaB = [&](int it, int stage) {
#pragma unroll
        for (int j = 0; j < 4; j++) {
            int ch = bChB + j;
            cpa16(bBase + stage * 32768 + bRow * 128 + ((ch ^ (bRow & 7)) << 4),
                  Wt + (size_t)bRow * DD + it * 64 + ch * 8);
        }
    };

    // ---- prologue: fill both stages; CONV keeps tile2 in regs ----
    if (CONV) {
        cpaB(0, 0); cpa_commit();
        cpaB(1, 1); cpa_commit();
        ldgA(0); stsA(0);
        ldgA(1); stsA(1);
        ldgA(2);                       // regA = tile2
    } else {
        cpaA(0, 0); cpaB(0, 0); cpa_commit();
        cpaA(1, 1); cpaB(1, 1); cpa_commit();
    }
    cpa_wait<1>();
    __syncthreads();

    // ---- mainloop: 4 tiles of BK=64 ----
#pragma unroll 1
    for (int it = 0; it < 4; it++) {
        const int s = it & 1;
        const uint32_t aSt = aBase + s * 16384;
        const uint32_t bSt = bBase + s * 32768;

#pragma unroll
        for (int ks = 0; ks < 4; ks++) {
            uint32_t afr[4][4];
#pragma unroll
            for (int mt = 0; mt < 4; mt++) {
                int m  = warpM + mt * 16 + (lane & 15);
                int ch = 2 * ks + (lane >> 4);
                ldsm4(afr[mt], aSt + m * 128 + ((ch ^ (m & 7)) << 4));
            }
            uint32_t bfr[2][4];
#pragma unroll
            for (int np = 0; np < 2; np++) {
                int n  = warpN + np * 16 + 8 * (lane >> 4) + (lane & 7);
                int ch = 2 * ks + ((lane >> 3) & 1);
                ldsm4(bfr[np], bSt + n * 128 + ((ch ^ (n & 7)) << 4));
            }
#pragma unroll
            for (int mt = 0; mt < 4; mt++)
#pragma unroll
                for (int np = 0; np < 2; np++) {
                    mma16(acc[mt][2 * np + 0], afr[mt], bfr[np] + 0);
                    mma16(acc[mt][2 * np + 1], afr[mt], bfr[np] + 2);
                }
        }
        if (it == 3) break;
        __syncthreads();                       // stage s free

        if (CONV) {
            if (it <= 1) stsA(s);              // tile it+2 from regA
            if (it == 0) ldgA(3);              // hidden under compute(it=1)
            if (it <= 1) { cpaB(it + 2, s); cpa_commit(); cpa_wait<1>(); }
            else         { cpa_wait<0>(); }
        } else {
            if (it <= 1) { cpaA(it + 2, s); cpaB(it + 2, s); cpa_commit(); cpa_wait<1>(); }
            else         { cpa_wait<0>(); }
        }
        __syncthreads();
    }

    // ---- epilogue: bias + relu (+mask), store fp16 ----
#pragma unroll
    for (int mt = 0; mt < 4; mt++) {
        int rr = rowBase + warpM + mt * 16 + grp;
#pragma unroll
        for (int pr = 0; pr < 2; pr++) {
            int r = rr + 8 * pr;
            float mv = 1.0f;
            if (mask != nullptr) mv = (mask[r] != 0) ? 1.0f : 0.0f;
#pragma unroll
            for (int nt = 0; nt < 4; nt++) {
                int col = warpN + nt * 8 + 2 * c4;
                float2 bb = *reinterpret_cast<const float2*>(bias + col);
                float v0 = fmaxf(acc[mt][nt][2 * pr + 0] + bb.x, 0.0f) * mv;
                float v1 = fmaxf(acc[mt][nt][2 * pr + 1] + bb.y, 0.0f) * mv;
                *reinterpret_cast<__half2*>(C + (size_t)r * DD + col) =
                    __floats2half2_rn(v0, v1);
            }
        }
    }
}

// ---------------------------------------------------------------------------
// Message passing: Out[b] (96 x 24576 fp32) = Ah[b] (96x96 fp16) @ H[b] (96x24576 fp16)
// 256 threads (8 warps), BN=128 col tile, BK=32 (3 tiles), warp tile 48x32.
// ---------------------------------------------------------------------------
__global__ __launch_bounds__(256)
void msg_h(const __half* __restrict__ Aall, const __half* __restrict__ H,
           float* __restrict__ Out)
{
    __shared__ __align__(16) char sm[96 * 208 + 2 * 8192];
    const uint32_t aB = (uint32_t)__cvta_generic_to_shared(sm);
    const uint32_t bB = aB + 19968;

    const int b = blockIdx.y;
    const int colBase = blockIdx.x * 128;
    const __half* Aab = Aall + (size_t)b * NN * NN;
    const __half* Hb  = H    + (size_t)b * NN * NCOLS;
    float*        Ob  = Out  + (size_t)b * NN * NCOLS;

    const int tid  = threadIdx.x;
    const int lane = tid & 31;
    const int warp = tid >> 5;
    const int grp  = lane >> 2;
    const int c4   = lane & 3;
    const int warpM = (warp >> 2) * 48;
    const int warpN = (warp & 3) * 32;

    const int bkr = tid >> 3;
    const int bch = tid & 7;
    auto cpaBt = [&](int it, int stage) {
#pragma unroll
        for (int j = 0; j < 2; j++) {
            int ch = bch + 8 * j;
            cpa16(bB + stage * 8192 + bkr * 256 + ((ch ^ (bkr & 7)) << 4),
                  Hb + (size_t)(it * 32 + bkr) * NCOLS + colBase + ch * 8);
        }
    };

    for (int idx = tid; idx < 96 * 12; idx += 256) {
        int row = idx / 12, ch = idx % 12;
        cpa16(aB + row * 208 + ch * 16, Aab + row * 96 + ch * 8);
    }
    cpaBt(0, 0); cpa_commit();
    cpaBt(1, 1); cpa_commit();
    cpa_wait<1>();
    __syncthreads();

    float acc[3][4][4];
#pragma unroll
    for (int i = 0; i < 3; i++)
#pragma unroll
        for (int j = 0; j < 4; j++)
#pragma unroll
            for (int r = 0; r < 4; r++) acc[i][j][r] = 0.0f;

#pragma unroll 1
    for (int it = 0; it < 3; it++) {
        const int st = it & 1;
#pragma unroll
        for (int sl = 0; sl < 2; sl++) {
            const int s = 2 * it + sl;
            uint32_t afr[3][4];
#pragma unroll
            for (int mt = 0; mt < 3; mt++) {
                int m  = warpM + mt * 16 + (lane & 15);
                int ch = 2 * s + (lane >> 4);
                ldsm4(afr[mt], aB + m * 208 + ch * 16);
            }
            uint32_t bfr[2][4];
#pragma unroll
            for (int np = 0; np < 2; np++) {
                int kl  = sl * 16 + (lane & 7) + 8 * ((lane >> 3) & 1);
                int chn = (warpN >> 3) + 2 * np + (lane >> 4);
                ldsm4t(bfr[np], bB + st * 8192 + kl * 256 + ((chn ^ (kl & 7)) << 4));
            }
#pragma unroll
            for (int mt = 0; mt < 3; mt++)
#pragma unroll
                for (int np = 0; np < 2; np++) {
                    mma16(acc[mt][2 * np + 0], afr[mt], bfr[np] + 0);
                    mma16(acc[mt][2 * np + 1], afr[mt], bfr[np] + 2);
                }
        }
        __syncthreads();
        if (it + 2 <= 2) { cpaBt(it + 2, st); cpa_commit(); cpa_wait<1>(); }
        else             { cpa_wait<0>(); }
        __syncthreads();
    }

#pragma unroll
    for (int mt = 0; mt < 3; mt++) {
        int rr = warpM + mt * 16 + grp;
#pragma unroll
        for (int pr = 0; pr < 2; pr++) {
            int r = rr + 8 * pr;
#pragma unroll
            for (int nt = 0; nt < 4; nt++) {
                int col = colBase + warpN + nt * 8 + 2 * c4;
                *reinterpret_cast<float2*>(Ob + (size_t)r * NCOLS + col) =
                    make_float2(acc[mt][nt][2 * pr + 0], acc[mt][nt][2 * pr + 1]);
            }
        }
    }
}

// ---------------------------------------------------------------------------
// kernel_launch: inputs X, mask, A, W1, b1, W2, b2
// ---------------------------------------------------------------------------
extern "C" void kernel_launch(void* const* d_in, const int* in_sizes, int n_in,
                              void* d_out, int out_size)
{
    const float* X    = (const float*)d_in[0];
    const int*   mask = (const int*)d_in[1];
    const float* Aadj = (const float*)d_in[2];
    const float* W1   = (const float*)d_in[3];
    const float* b1   = (const float*)d_in[4];
    const float* W2   = (const float*)d_in[5];
    const float* b2   = (const float*)d_in[6];
    float*       out  = (float*)d_out;

    __half *h1, *h2, *w1h, *w2h, *ah;
    cudaGetSymbolAddress((void**)&h1,  g_h1);
    cudaGetSymbolAddress((void**)&h2,  g_h2);
    cudaGetSymbolAddress((void**)&w1h, g_W1h);
    cudaGetSymbolAddress((void**)&w2h, g_W2h);
    cudaGetSymbolAddress((void**)&ah,  g_Ah);

    const int MLP_SMEM = 98304;   // 96KB
    cudaFuncSetAttribute(mlp_h3<1>, cudaFuncAttributeMaxDynamicSharedMemorySize, MLP_SMEM);
    cudaFuncSetAttribute(mlp_h3<0>, cudaFuncAttributeMaxDynamicSharedMemorySize, MLP_SMEM);

    // prepasses: transpose+cvt W1/W2 to fp16 [n][k]; cvt Aadj to fp16
    {
        dim3 tg(DD / 32, DD / 32);
        dim3 tb(32, 8);
        transpose_cvt_kernel<<<tg, tb>>>(W1, w1h);
        transpose_cvt_kernel<<<tg, tb>>>(W2, w2h);
        int a4 = (BB * NN * NN) / 4;
        cvt_half_kernel<<<(a4 + 255) / 256, 256>>>((const float4*)Aadj, (uint2*)ah, a4);
    }

    // layer 1: h1 = half(relu(half(X) @ W1 + b1))
    mlp_h3<1><<<MROWS / 128, 512, MLP_SMEM>>>(X, w1h, b1, nullptr, h1);
    // layer 2: h2 = half(mask * relu(h1 @ W2 + b2))
    mlp_h3<0><<<MROWS / 128, 512, MLP_SMEM>>>(h1, w2h, b2, mask, h2);
    // message passing: out[b] = Ah[b] @ h2[b]
    {
        dim3 grid(NCOLS / 128, BB);   // (192, 16)
        msg_h<<<grid, 256>>>(ah, h2, out);
    }
}

// round 10
// speedup vs baseline: 1.5120x; 1.0897x over previous
#include <cuda_runtime.h>
#include <cuda_fp16.h>
#include <cstdint>
#include <cstddef>

#define BB 16
#define NN 96
#define DD 256
#define MROWS (BB * NN * NN)          // 147456
#define NCOLS (NN * DD)               // 24576

// Scratch (allocation-free device globals)
__device__ __half g_h2[(size_t)MROWS * DD];
__device__ __half g_W1h[DD * DD];    // transposed [n][k] fp16
__device__ __half g_W2h[DD * DD];    // transposed [n][k] fp16
__device__ __half g_Ah[BB * NN * NN];

// ---------------------------------------------------------------------------
// helpers
// ---------------------------------------------------------------------------
__device__ __forceinline__ uint32_t packh2(float a, float b) {
    __half2 h = __floats2half2_rn(a, b);
    return *reinterpret_cast<uint32_t*>(&h);
}

__device__ __forceinline__ void mma16(float* c, const uint32_t* a, const uint32_t* b) {
    asm volatile("mma.sync.aligned.m16n8k16.row.col.f32.f16.f16.f32 "
        "{%0,%1,%2,%3}, {%4,%5,%6,%7}, {%8,%9}, {%0,%1,%2,%3};"
        : "+f"(c[0]), "+f"(c[1]), "+f"(c[2]), "+f"(c[3])
        : "r"(a[0]), "r"(a[1]), "r"(a[2]), "r"(a[3]), "r"(b[0]), "r"(b[1]));
}

__device__ __forceinline__ void ldsm4(uint32_t* r, uint32_t addr) {
    asm volatile("ldmatrix.sync.aligned.m8n8.x4.shared.b16 {%0,%1,%2,%3}, [%4];"
        : "=r"(r[0]), "=r"(r[1]), "=r"(r[2]), "=r"(r[3]) : "r"(addr));
}

__device__ __forceinline__ void ldsm4t(uint32_t* r, uint32_t addr) {
    asm volatile("ldmatrix.sync.aligned.m8n8.x4.trans.shared.b16 {%0,%1,%2,%3}, [%4];"
        : "=r"(r[0]), "=r"(r[1]), "=r"(r[2]), "=r"(r[3]) : "r"(addr));
}

__device__ __forceinline__ void cpa16(uint32_t dst, const void* src) {
    asm volatile("cp.async.cg.shared.global [%0], [%1], 16;\n" :: "r"(dst), "l"(src));
}
__device__ __forceinline__ void cpa_commit() {
    asm volatile("cp.async.commit_group;\n");
}
template <int N>
__device__ __forceinline__ void cpa_wait() {
    asm volatile("cp.async.wait_group %0;\n" :: "n"(N));
}

// ---------------------------------------------------------------------------
// prepasses
// ---------------------------------------------------------------------------
__global__ void transpose_cvt_kernel(const float* __restrict__ src,
                                     __half* __restrict__ dst) {
    __shared__ float t[32][33];
    int bx = blockIdx.x * 32;
    int by = blockIdx.y * 32;
    int x = threadIdx.x, y0 = threadIdx.y;
#pragma unroll
    for (int r = 0; r < 32; r += 8)
        t[y0 + r][x] = src[(size_t)(by + y0 + r) * DD + bx + x];
    __syncthreads();
#pragma unroll
    for (int r = 0; r < 32; r += 8)
        dst[(size_t)(bx + y0 + r) * DD + by + x] = __float2half_rn(t[x][y0 + r]);
}

__global__ void cvt_half_kernel(const float4* __restrict__ src,
                                uint2* __restrict__ dst, int n4) {
    int i = blockIdx.x * blockDim.x + threadIdx.x;
    if (i < n4) {
        float4 v = src[i];
        uint2 o;
        o.x = packh2(v.x, v.y);
        o.y = packh2(v.z, v.w);
        dst[i] = o;
    }
}

// ---------------------------------------------------------------------------
// Fused 2-layer MLP: h2 = mask * relu( relu(X@W1+b1) @ W2 + b2 ), fp16 out.
// Per CTA: M=128 rows, N=256 (full D), K=256 per GEMM (4 tiles of 64).
// 512 threads (16 warps), warp tile 64x32. smem: A 4x16KB (X -> h1 in place),
// B 2x32KB cp.async double buffer (W1 then W2). 128KB total, ~125 regs.
// ---------------------------------------------------------------------------
__global__ __launch_bounds__(512)
void mlp_fused(const float* __restrict__ X, const __half* __restrict__ W1t,
               const __half* __restrict__ W2t, const float* __restrict__ b1,
               const float* __restrict__ b2, const int* __restrict__ mask,
               __half* __restrict__ C)
{
    extern __shared__ __align__(16) char smem[];
    const uint32_t sBase = (uint32_t)__cvta_generic_to_shared(smem);
    const uint32_t aBase = sBase;             // 4 tiles x 16KB = 64KB
    const uint32_t bBase = sBase + 65536;     // 2 stages x 32KB

    const int tid  = threadIdx.x;
    const int lane = tid & 31;
    const int warp = tid >> 5;                // 0..15
    const int grp  = lane >> 2;
    const int c4   = lane & 3;
    const int warpM = (warp >> 3) * 64;       // 0 / 64
    const int warpN = (warp & 7) * 32;        // 0..224
    const int rowBase = blockIdx.x * 128;

    // A loader: 128 rows x 8 chunks, 512 thr -> 2 chunks/thread
    const int aRow = tid >> 2;                // 0..127
    const int aChB = (tid & 3) * 2;           // 0,2,4,6
    // B loader: 256 rows x 8 chunks -> 4 chunks/thread
    const int bRow = tid >> 1;                // 0..255
    const int bChB = (tid & 1) * 4;           // 0,4

    uint4 regA[2];

    float acc[4][4][4];
#pragma unroll
    for (int i = 0; i < 4; i++)
#pragma unroll
        for (int j = 0; j < 4; j++)
#pragma unroll
            for (int r = 0; r < 4; r++) acc[i][j][r] = 0.0f;

    auto ldgA = [&](int t) {
#pragma unroll
        for (int j = 0; j < 2; j++) {
            const float* p = X + (size_t)(rowBase + aRow) * DD + t * 64 + (aChB + j) * 8;
            float4 u = *reinterpret_cast<const float4*>(p);
            float4 v = *reinterpret_cast<const float4*>(p + 4);
            regA[j].x = packh2(u.x, u.y);
            regA[j].y = packh2(u.z, u.w);
            regA[j].z = packh2(v.x, v.y);
            regA[j].w = packh2(v.z, v.w);
        }
    };
    auto stsA = [&](int t) {
#pragma unroll
        for (int j = 0; j < 2; j++) {
            int ch = aChB + j;
            *reinterpret_cast<uint4*>(smem + t * 16384 + aRow * 128 +
                                      ((ch ^ (aRow & 7)) << 4)) = regA[j];
        }
    };
    auto cpaB = [&](const __half* Wt, int t, int stage) {
#pragma unroll
        for (int j = 0; j < 4; j++) {
            int ch = bChB + j;
            cpa16(bBase + stage * 32768 + bRow * 128 + ((ch ^ (bRow & 7)) << 4),
                  Wt + (size_t)bRow * DD + t * 64 + ch * 8);
        }
    };

    auto computeTile = [&](uint32_t aSt, uint32_t bSt) {
#pragma unroll
        for (int ks = 0; ks < 4; ks++) {
            uint32_t afr[4][4];
#pragma unroll
            for (int mt = 0; mt < 4; mt++) {
                int m  = warpM + mt * 16 + (lane & 15);
                int ch = 2 * ks + (lane >> 4);
                ldsm4(afr[mt], aSt + m * 128 + ((ch ^ (m & 7)) << 4));
            }
            uint32_t bfr[2][4];
#pragma unroll
            for (int np = 0; np < 2; np++) {
                int n  = warpN + np * 16 + 8 * (lane >> 4) + (lane & 7);
                int ch = 2 * ks + ((lane >> 3) & 1);
                ldsm4(bfr[np], bSt + n * 128 + ((ch ^ (n & 7)) << 4));
            }
#pragma unroll
            for (int mt = 0; mt < 4; mt++)
#pragma unroll
                for (int np = 0; np < 2; np++) {
                    mma16(acc[mt][2 * np + 0], afr[mt], bfr[np] + 0);
                    mma16(acc[mt][2 * np + 1], afr[mt], bfr[np] + 2);
                }
        }
    };

    // ---- prologue: W1 tiles 0,1 in flight; X tiles 0,1 staged; tile2 in regs
    cpaB(W1t, 0, 0); cpa_commit();            // G0
    cpaB(W1t, 1, 1); cpa_commit();            // G1
    ldgA(0); stsA(0);
    ldgA(1); stsA(1);
    ldgA(2);                                  // regA = X tile2
    cpa_wait<1>();                            // G0 done
    __syncthreads();

    // ---- GEMM1: h1 = X @ W1 ----
#pragma unroll 1
    for (int t = 0; t < 4; t++) {
        computeTile(aBase + t * 16384, bBase + (t & 1) * 32768);
        __syncthreads();                      // all reads of stage t&1 / A done
        if (t == 0) {
            stsA(2); ldgA(3);
            cpaB(W1t, 2, 0); cpa_commit();    // G2
            cpa_wait<1>();                    // G1 done
        } else if (t == 1) {
            stsA(3);
            cpaB(W1t, 3, 1); cpa_commit();    // G3
            cpa_wait<1>();                    // G2 done
        } else if (t == 2) {
            cpaB(W2t, 0, 0); cpa_commit();    // G4 (W2 prefetch into s0)
            cpa_wait<1>();                    // G3 done
        }
        __syncthreads();
    }

    // ---- epilogue1: h1 = relu(acc + b1) -> smem A region (fp16), zero acc
#pragma unroll
    for (int mt = 0; mt < 4; mt++) {
#pragma unroll
        for (int pr = 0; pr < 2; pr++) {
            int rl = warpM + mt * 16 + grp + 8 * pr;   // 0..127
#pragma unroll
            for (int nt = 0; nt < 4; nt++) {
                int col = warpN + nt * 8 + 2 * c4;
                float2 bb = *reinterpret_cast<const float2*>(b1 + col);
                float v0 = fmaxf(acc[mt][nt][2 * pr + 0] + bb.x, 0.0f);
                float v1 = fmaxf(acc[mt][nt][2 * pr + 1] + bb.y, 0.0f);
                int tt = col >> 6;
                int ch = (col & 63) >> 3;
                *reinterpret_cast<uint32_t*>(smem + tt * 16384 + rl * 128 +
                    ((ch ^ (rl & 7)) << 4) + (col & 7) * 2) = packh2(v0, v1);
            }
        }
    }
#pragma unroll
    for (int i = 0; i < 4; i++)
#pragma unroll
        for (int j = 0; j < 4; j++)
#pragma unroll
            for (int r = 0; r < 4; r++) acc[i][j][r] = 0.0f;

    cpaB(W2t, 1, 1); cpa_commit();            // G5 (s1 free after t=3)
    cpa_wait<1>();                            // G4 done (s0 = W2 tile0)
    __syncthreads();                          // h1 visible + G4 chip-wide

    // ---- GEMM2: h2 = h1 @ W2 ----
#pragma unroll 1
    for (int u = 0; u < 4; u++) {
        computeTile(aBase + u * 16384, bBase + (u & 1) * 32768);
        __syncthreads();
        if (u == 0) {
            cpaB(W2t, 2, 0); cpa_commit();    // G6
            cpa_wait<1>();                    // G5 done
        } else if (u == 1) {
            cpaB(W2t, 3, 1); cpa_commit();    // G7
            cpa_wait<1>();                    // G6 done
        } else if (u == 2) {
            cpa_wait<0>();                    // G7 done
        }
        __syncthreads();
    }

    // ---- epilogue2: h2 = mask * relu(acc + b2) -> gmem fp16
#pragma unroll
    for (int mt = 0; mt < 4; mt++) {
        int rr = rowBase + warpM + mt * 16 + grp;
#pragma unroll
        for (int pr = 0; pr < 2; pr++) {
            int r = rr + 8 * pr;
            float mv = (mask[r] != 0) ? 1.0f : 0.0f;
#pragma unroll
            for (int nt = 0; nt < 4; nt++) {
                int col = warpN + nt * 8 + 2 * c4;
                float2 bb = *reinterpret_cast<const float2*>(b2 + col);
                float v0 = fmaxf(acc[mt][nt][2 * pr + 0] + bb.x, 0.0f) * mv;
                float v1 = fmaxf(acc[mt][nt][2 * pr + 1] + bb.y, 0.0f) * mv;
                *reinterpret_cast<__half2*>(C + (size_t)r * DD + col) =
                    __floats2half2_rn(v0, v1);
            }
        }
    }
}

// ---------------------------------------------------------------------------
// Message passing: Out[b] (96 x 24576 fp32) = Ah[b] (96x96 fp16) @ H[b] fp16
// 256 threads (8 warps), BN=128, BK=32 (3 tiles), warp tile 48x32. (proven)
// ---------------------------------------------------------------------------
__global__ __launch_bounds__(256)
void msg_h(const __half* __restrict__ Aall, const __half* __restrict__ H,
           float* __restrict__ Out)
{
    __shared__ __align__(16) char sm[96 * 208 + 2 * 8192];
    const uint32_t aB = (uint32_t)__cvta_generic_to_shared(sm);
    const uint32_t bB = aB + 19968;

    const int b = blockIdx.y;
    const int colBase = blockIdx.x * 128;
    const __half* Aab = Aall + (size_t)b * NN * NN;
    const __half* Hb  = H    + (size_t)b * NN * NCOLS;
    float*        Ob  = Out  + (size_t)b * NN * NCOLS;

    const int tid  = threadIdx.x;
    const int lane = tid & 31;
    const int warp = tid >> 5;
    const int grp  = lane >> 2;
    const int c4   = lane & 3;
    const int warpM = (warp >> 2) * 48;
    const int warpN = (warp & 3) * 32;

    const int bkr = tid >> 3;
    const int bch = tid & 7;
    auto cpaBt = [&](int it, int stage) {
#pragma unroll
        for (int j = 0; j < 2; j++) {
            int ch = bch + 8 * j;
            cpa16(bB + stage * 8192 + bkr * 256 + ((ch ^ (bkr & 7)) << 4),
                  Hb + (size_t)(it * 32 + bkr) * NCOLS + colBase + ch * 8);
        }
    };

    for (int idx = tid; idx < 96 * 12; idx += 256) {
        int row = idx / 12, ch = idx % 12;
        cpa16(aB + row * 208 + ch * 16, Aab + row * 96 + ch * 8);
    }
    cpaBt(0, 0); cpa_commit();
    cpaBt(1, 1); cpa_commit();
    cpa_wait<1>();
    __syncthreads();

    float acc[3][4][4];
#pragma unroll
    for (int i = 0; i < 3; i++)
#pragma unroll
        for (int j = 0; j < 4; j++)
#pragma unroll
            for (int r = 0; r < 4; r++) acc[i][j][r] = 0.0f;

#pragma unroll 1
    for (int it = 0; it < 3; it++) {
        const int st = it & 1;
#pragma unroll
        for (int sl = 0; sl < 2; sl++) {
            const int s = 2 * it + sl;
            uint32_t afr[3][4];
#pragma unroll
            for (int mt = 0; mt < 3; mt++) {
                int m  = warpM + mt * 16 + (lane & 15);
                int ch = 2 * s + (lane >> 4);
                ldsm4(afr[mt], aB + m * 208 + ch * 16);
            }
            uint32_t bfr[2][4];
#pragma unroll
            for (int np = 0; np < 2; np++) {
                int kl  = sl * 16 + (lane & 7) + 8 * ((lane >> 3) & 1);
                int chn = (warpN >> 3) + 2 * np + (lane >> 4);
                ldsm4t(bfr[np], bB + st * 8192 + kl * 256 + ((chn ^ (kl & 7)) << 4));
            }
#pragma unroll
            for (int mt = 0; mt < 3; mt++)
#pragma unroll
                for (int np = 0; np < 2; np++) {
                    mma16(acc[mt][2 * np + 0], afr[mt], bfr[np] + 0);
                    mma16(acc[mt][2 * np + 1], afr[mt], bfr[np] + 2);
                }
        }
        __syncthreads();
        if (it + 2 <= 2) { cpaBt(it + 2, st); cpa_commit(); cpa_wait<1>(); }
        else             { cpa_wait<0>(); }
        __syncthreads();
    }

#pragma unroll
    for (int mt = 0; mt < 3; mt++) {
        int rr = warpM + mt * 16 + grp;
#pragma unroll
        for (int pr = 0; pr < 2; pr++) {
            int r = rr + 8 * pr;
#pragma unroll
            for (int nt = 0; nt < 4; nt++) {
                int col = colBase + warpN + nt * 8 + 2 * c4;
                *reinterpret_cast<float2*>(Ob + (size_t)r * NCOLS + col) =
                    make_float2(acc[mt][nt][2 * pr + 0], acc[mt][nt][2 * pr + 1]);
            }
        }
    }
}

// ---------------------------------------------------------------------------
// kernel_launch: inputs X, mask, A, W1, b1, W2, b2
// ---------------------------------------------------------------------------
extern "C" void kernel_launch(void* const* d_in, const int* in_sizes, int n_in,
                              void* d_out, int out_size)
{
    const float* X    = (const float*)d_in[0];
    const int*   mask = (const int*)d_in[1];
    const float* Aadj = (const float*)d_in[2];
    const float* W1   = (const float*)d_in[3];
    const float* b1   = (const float*)d_in[4];
    const float* W2   = (const float*)d_in[5];
    const float* b2   = (const float*)d_in[6];
    float*       out  = (float*)d_out;

    __half *h2, *w1h, *w2h, *ah;
    cudaGetSymbolAddress((void**)&h2,  g_h2);
    cudaGetSymbolAddress((void**)&w1h, g_W1h);
    cudaGetSymbolAddress((void**)&w2h, g_W2h);
    cudaGetSymbolAddress((void**)&ah,  g_Ah);

    const int FUSED_SMEM = 65536 + 65536;    // 128KB
    cudaFuncSetAttribute(mlp_fused, cudaFuncAttributeMaxDynamicSharedMemorySize, FUSED_SMEM);

    // prepasses: transpose+cvt W1/W2 to fp16 [n][k]; cvt Aadj to fp16
    {
        dim3 tg(DD / 32, DD / 32);
        dim3 tb(32, 8);
        transpose_cvt_kernel<<<tg, tb>>>(W1, w1h);
        transpose_cvt_kernel<<<tg, tb>>>(W2, w2h);
        int a4 = (BB * NN * NN) / 4;
        cvt_half_kernel<<<(a4 + 255) / 256, 256>>>((const float4*)Aadj, (uint2*)ah, a4);
    }

    // fused MLP: h2 = mask * relu(relu(X@W1+b1)@W2+b2)
    mlp_fused<<<MROWS / 128, 512, FUSED_SMEM>>>(X, w1h, w2h, b1, b2, mask, h2);

    // message passing: out[b] = Ah[b] @ h2[b]
    {
        dim3 grid(NCOLS / 128, BB);   // (192, 16)
        msg_h<<<grid, 256>>>(ah, h2, out);
    }
}